// round 15
// baseline (speedup 1.0000x reference)
#include <cuda_runtime.h>
#include <cuda_fp16.h>
#include <math.h>

#define N_NODES 20000
#define N_EDGES 5000
#define D       128
#define ATT     32
#define ECAP    384
#define NCAP    128
#define LN_EPS  1e-5f
#define DEG_EPS 1e-12f
#define FULL    0xffffffffu
#define E4      (N_EDGES / 4)    // 1250 float4 per H row
#define WPR     160              // bitmask words per node row (5120 bits)
#define TWPR    625              // transposed words per edge row (20000 bits)

#if defined(__CUDA_ARCH__) && __CUDA_ARCH__ >= 900
#define GRID_DEP_SYNC() cudaGridDependencySynchronize()
#define PDL_TRIGGER()   cudaTriggerProgrammaticLaunchCompletion()
#else
#define GRID_DEP_SYNC()
#define PDL_TRIGGER()
#endif

// ---------------- device scratch ----------------
__device__ int   g_edge_cnt[N_EDGES];
__device__ int   g_node_cnt[N_NODES];
__device__ int   g_edge_nodes[N_EDGES * ECAP];
__device__ int   g_node_edges[N_NODES * NCAP];
__device__ unsigned g_bits [N_NODES * WPR];    // 12.8 MB node-major bitmask
__device__ unsigned g_bitsT[5120 * TWPR];      // 12.8 MB edge-major bitmask
__device__ float g_de_inv[N_EDGES];
__device__ float g_dv_inv[N_NODES];
__device__ uint4  g_x[N_NODES * 16];           // fp16 features (256B rows, 16 uint4)
__device__ uint4  g_edge_h[N_EDGES * 16];      // fp16 edge means
__device__ float4 g_edge_out[N_EDGES * 32];    // fp32 final edge_out
__device__ float g_logits[N_EDGES];

// ---------------- fp16 helpers ----------------
__device__ __forceinline__ uint2 f4_to_h4(float4 v) {
    __half2 a = __floats2half2_rn(v.x, v.y);
    __half2 b = __floats2half2_rn(v.z, v.w);
    uint2 r; r.x = *(unsigned*)&a; r.y = *(unsigned*)&b; return r;
}
__device__ __forceinline__ __half2 u2h(unsigned u) { return *(__half2*)&u; }
__device__ __forceinline__ void add8(float* fs, uint4 v) {
    float2 f0 = __half22float2(u2h(v.x));
    float2 f1 = __half22float2(u2h(v.y));
    float2 f2 = __half22float2(u2h(v.z));
    float2 f3 = __half22float2(u2h(v.w));
    fs[0] += f0.x; fs[1] += f0.y; fs[2] += f1.x; fs[3] += f1.y;
    fs[4] += f2.x; fs[5] += f2.y; fs[6] += f3.x; fs[7] += f3.y;
}

// ---------------- phase 1: scan (x0 conversion folded in) ----------------
__global__ void __launch_bounds__(256) scan_kernel(const float* __restrict__ H,
                                                   const float4* __restrict__ x0) {
    // folded init: x0 -> fp16
    {
        int i = blockIdx.x * blockDim.x + threadIdx.x;
        int stride = gridDim.x * blockDim.x;
        uint2* xp = (uint2*)g_x;
        for (int k = i; k < N_NODES * 32; k += stride) xp[k] = f4_to_h4(__ldg(&x0[k]));
    }
    int gw = (blockIdx.x * blockDim.x + threadIdx.x) >> 5;
    int lane = threadIdx.x & 31;
    if (gw >= N_NODES) return;
    const float4* row = (const float4*)H + (size_t)gw * E4;
    int* nlist = &g_node_edges[gw * NCAP];
    unsigned* brow = &g_bits[gw * WPR];
    unsigned lt = (1u << lane) - 1u;
    int nbase = 0;
    for (int c = 0; c < 10; c++) {
        float4 v[4];
        #pragma unroll
        for (int u = 0; u < 4; u++) {
            int i = (c * 4 + u) * 32 + lane;
            v[u] = make_float4(0.f, 0.f, 0.f, 0.f);
            if (i < E4) v[u] = __ldg(&row[i]);
        }
        #pragma unroll
        for (int u = 0; u < 4; u++) {
            int g = c * 4 + u;
            int i = g * 32 + lane;
            unsigned b0 = __ballot_sync(FULL, v[u].x != 0.f);
            unsigned b1 = __ballot_sync(FULL, v[u].y != 0.f);
            unsigned b2 = __ballot_sync(FULL, v[u].z != 0.f);
            unsigned b3 = __ballot_sync(FULL, v[u].w != 0.f);
            unsigned bw = (lane == 0) ? b0 : (lane == 1) ? b1 : (lane == 2) ? b2 : b3;
            if (lane < 4) brow[4 * g + lane] = bw;
            int p0 = __popc(b0), p1 = __popc(b1), p2 = __popc(b2);
            int total = p0 + p1 + p2 + __popc(b3);
            int e = i * 4;
            int slot;
            if (v[u].x != 0.f) { slot = nbase + __popc(b0 & lt);
                                 if (slot < NCAP) nlist[slot] = e; }
            if (v[u].y != 0.f) { slot = nbase + p0 + __popc(b1 & lt);
                                 if (slot < NCAP) nlist[slot] = e + 1; }
            if (v[u].z != 0.f) { slot = nbase + p0 + p1 + __popc(b2 & lt);
                                 if (slot < NCAP) nlist[slot] = e + 2; }
            if (v[u].w != 0.f) { slot = nbase + p0 + p1 + p2 + __popc(b3 & lt);
                                 if (slot < NCAP) nlist[slot] = e + 3; }
            nbase += total;
        }
    }
    if (lane == 0) {
        g_node_cnt[gw] = nbase;
        g_dv_inv[gw] = 1.0f / fmaxf((float)nbase, DEG_EPS);
    }
}

// ---------------- phase 2: 32x32 bit-tile transpose ----------------
__global__ void __launch_bounds__(256) transpose_kernel() {
    GRID_DEP_SYNC();
    int warp = (blockIdx.x * blockDim.x + threadIdx.x) >> 5;
    if (warp >= TWPR * WPR) return;
    int I = warp / WPR;
    int J = warp - I * WPR;
    int lane = threadIdx.x & 31;
    unsigned x = g_bits[(I * 32 + lane) * WPR + J];
    PDL_TRIGGER();
    #pragma unroll
    for (int s = 16; s > 0; s >>= 1) {
        unsigned m = (s == 16) ? 0x0000FFFFu : (s == 8) ? 0x00FF00FFu :
                     (s == 4) ? 0x0F0F0F0Fu : (s == 2) ? 0x33333333u : 0x55555555u;
        unsigned y = __shfl_xor_sync(FULL, x, s);
        x = ((lane & s) == 0) ? ((x & m) | ((y & m) << s))
                              : ((x & ~m) | ((y & ~m) >> s));
    }
    g_bitsT[(J * 32 + lane) * TWPR + I] = x;
}

// ---------------- phase 3: 4 warps/edge emit ----------------
#define QW 157
__global__ void __launch_bounds__(128) emit_kernel() {
    GRID_DEP_SYNC();
    int e = blockIdx.x;
    int w = threadIdx.x >> 5;
    int lane = threadIdx.x & 31;
    int g = e >> 7, rem = e & 127;
    int r = 128 * g + 32 * (rem & 3) + (rem >> 2);
    const unsigned* row = &g_bitsT[r * TWPR];
    int* lst = &g_edge_nodes[e * ECAP];
    __shared__ int wtot[4];

    int q0 = w * QW;
    int q1 = min(q0 + QW, TWPR);

    int cnt = 0;
    for (int i = q0 + lane; i < q1; i += 32) cnt += __popc(row[i]);
    #pragma unroll
    for (int o = 16; o > 0; o >>= 1) cnt += __shfl_xor_sync(FULL, cnt, o);
    if (lane == 0) wtot[w] = cnt;
    __syncthreads();
    PDL_TRIGGER();
    int base = 0;
    #pragma unroll
    for (int j = 0; j < 4; j++) if (j < w) base += wtot[j];

    int nbase = base;
    for (int b = q0; b < q1; b += 32) {
        int i = b + lane;
        unsigned word = (i < q1) ? row[i] : 0u;
        int c = __popc(word);
        int pref = c;
        #pragma unroll
        for (int o = 1; o < 32; o <<= 1) {
            int t = __shfl_up_sync(FULL, pref, o);
            if (lane >= o) pref += t;
        }
        int total = __shfl_sync(FULL, pref, 31);
        int slot = nbase + pref - c;
        while (word) {
            int bb = __ffs(word) - 1;
            word &= word - 1;
            if (slot < ECAP) lst[slot] = i * 32 + bb;
            slot++;
        }
        nbase += total;
    }
    if (w == 3 && lane == 0) {
        int tot = wtot[0] + wtot[1] + wtot[2] + wtot[3];
        g_edge_cnt[e] = tot;
        g_de_inv[e] = 1.0f / fmaxf((float)tot, DEG_EPS);
    }
}

// ---------------- V -> E mean: 4 warps/edge (R11-exact); FINAL also does logits ----------------
template <bool FINAL>
__global__ void __launch_bounds__(128) v2e_kernel(const float* __restrict__ W,
                                                  const float* __restrict__ bA,
                                                  const float* __restrict__ qA) {
    GRID_DEP_SYNC();
    int e = blockIdx.x;
    int w = threadIdx.x >> 5;
    int lane = threadIdx.x & 31;
    int half = lane >> 4;
    int sub = lane & 15;
    __shared__ float part[4][128];

    int deg = min(g_edge_cnt[e], ECAP);
    const int* lst = &g_edge_nodes[e * ECAP];
    int q = (deg + 3) >> 2;
    int start = w * q;
    int end = min(start + q, deg);

    __half2 z = __floats2half2_rn(0.f, 0.f);
    __half2 a0 = z, a1 = z, a2 = z, a3 = z, b0 = z, b1 = z, b2 = z, b3 = z;
    float fs[8] = {0.f, 0.f, 0.f, 0.f, 0.f, 0.f, 0.f, 0.f};

    for (int base = start; base < end; base += 32) {
        int m = min(32, end - base);
        int idx = lst[base + min(lane, m - 1)];
        int k = 0;
        for (; k + 4 <= m; k += 4) {
            int na = __shfl_sync(FULL, idx, k + half);
            int nb = __shfl_sync(FULL, idx, k + 2 + half);
            uint4 va = g_x[na * 16 + sub];
            uint4 vb = g_x[nb * 16 + sub];
            if (FINAL) {
                add8(fs, va); add8(fs, vb);
            } else {
                a0 = __hadd2(a0, u2h(va.x)); a1 = __hadd2(a1, u2h(va.y));
                a2 = __hadd2(a2, u2h(va.z)); a3 = __hadd2(a3, u2h(va.w));
                b0 = __hadd2(b0, u2h(vb.x)); b1 = __hadd2(b1, u2h(vb.y));
                b2 = __hadd2(b2, u2h(vb.z)); b3 = __hadd2(b3, u2h(vb.w));
            }
        }
        for (; k + 2 <= m; k += 2) {
            int na = __shfl_sync(FULL, idx, k + half);
            uint4 va = g_x[na * 16 + sub];
            if (FINAL) {
                add8(fs, va);
            } else {
                a0 = __hadd2(a0, u2h(va.x)); a1 = __hadd2(a1, u2h(va.y));
                a2 = __hadd2(a2, u2h(va.z)); a3 = __hadd2(a3, u2h(va.w));
            }
        }
        if (k < m) {
            int na = __shfl_sync(FULL, idx, k);
            if (half == 0) {
                uint4 va = g_x[na * 16 + sub];
                if (FINAL) {
                    add8(fs, va);
                } else {
                    a0 = __hadd2(a0, u2h(va.x)); a1 = __hadd2(a1, u2h(va.y));
                    a2 = __hadd2(a2, u2h(va.z)); a3 = __hadd2(a3, u2h(va.w));
                }
            }
        }
    }
    PDL_TRIGGER();
    if (!FINAL) {
        a0 = __hadd2(a0, b0); a1 = __hadd2(a1, b1);
        a2 = __hadd2(a2, b2); a3 = __hadd2(a3, b3);
        float2 f0 = __half22float2(a0), f1 = __half22float2(a1);
        float2 f2 = __half22float2(a2), f3 = __half22float2(a3);
        fs[0] = f0.x; fs[1] = f0.y; fs[2] = f1.x; fs[3] = f1.y;
        fs[4] = f2.x; fs[5] = f2.y; fs[6] = f3.x; fs[7] = f3.y;
    }
    // cross-half merge
    #pragma unroll
    for (int i = 0; i < 8; i++) fs[i] += __shfl_xor_sync(FULL, fs[i], 16);
    if (half == 0) {
        #pragma unroll
        for (int i = 0; i < 8; i++) part[w][sub * 8 + i] = fs[i];
    }
    __syncthreads();
    if (w == 0) {
        float4 p0 = *(const float4*)&part[0][lane * 4];
        float4 p1 = *(const float4*)&part[1][lane * 4];
        float4 p2 = *(const float4*)&part[2][lane * 4];
        float4 p3 = *(const float4*)&part[3][lane * 4];
        float s = g_de_inv[e];
        float4 r;
        r.x = ((p0.x + p1.x) + (p2.x + p3.x)) * s;
        r.y = ((p0.y + p1.y) + (p2.y + p3.y)) * s;
        r.z = ((p0.z + p1.z) + (p2.z + p3.z)) * s;
        r.w = ((p0.w + p1.w) + (p2.w + p3.w)) * s;
        if (FINAL) {
            g_edge_out[e * 32 + lane] = r;
            // fused logits: warp 0 holds the full 128-dim row (4 dims/lane)
            float acc = 0.0f;
            #pragma unroll 8
            for (int k = 0; k < 32; k++) {
                float fx = __shfl_sync(FULL, r.x, k);
                float fy = __shfl_sync(FULL, r.y, k);
                float fz = __shfl_sync(FULL, r.z, k);
                float fw = __shfl_sync(FULL, r.w, k);
                acc += fx * __ldg(&W[(4 * k + 0) * ATT + lane]);
                acc += fy * __ldg(&W[(4 * k + 1) * ATT + lane]);
                acc += fz * __ldg(&W[(4 * k + 2) * ATT + lane]);
                acc += fw * __ldg(&W[(4 * k + 3) * ATT + lane]);
            }
            float t = tanhf(acc + __ldg(&bA[lane])) * __ldg(&qA[lane]);
            #pragma unroll
            for (int o = 16; o > 0; o >>= 1) t += __shfl_xor_sync(FULL, t, o);
            if (lane == 0) g_logits[e] = t;
        } else {
            ((uint2*)g_edge_h)[e * 32 + lane] = f4_to_h4(r);
        }
    }
}

// ---------------- E -> V mean + residual + LayerNorm (R11-exact) ----------------
__global__ void __launch_bounds__(256) e2v_ln_kernel(const float4* __restrict__ x0,
                                                     const float4* __restrict__ gamma4,
                                                     const float4* __restrict__ beta4) {
    GRID_DEP_SYNC();
    int n = (blockIdx.x * blockDim.x + threadIdx.x) >> 5;
    int lane = threadIdx.x & 31;
    int half = lane >> 4;
    int sub = lane & 15;
    int deg = min(g_node_cnt[n], NCAP);
    const int* lst = &g_node_edges[n * NCAP];

    __half2 z = __floats2half2_rn(0.f, 0.f);
    __half2 a0 = z, a1 = z, a2 = z, a3 = z, b0 = z, b1 = z, b2 = z, b3 = z;

    for (int base = 0; base < deg; base += 32) {
        int m = min(32, deg - base);
        int idx = lst[base + min(lane, m - 1)];
        int k = 0;
        for (; k + 4 <= m; k += 4) {
            int ea = __shfl_sync(FULL, idx, k + half);
            int eb = __shfl_sync(FULL, idx, k + 2 + half);
            uint4 va = g_edge_h[ea * 16 + sub];
            uint4 vb = g_edge_h[eb * 16 + sub];
            a0 = __hadd2(a0, u2h(va.x)); a1 = __hadd2(a1, u2h(va.y));
            a2 = __hadd2(a2, u2h(va.z)); a3 = __hadd2(a3, u2h(va.w));
            b0 = __hadd2(b0, u2h(vb.x)); b1 = __hadd2(b1, u2h(vb.y));
            b2 = __hadd2(b2, u2h(vb.z)); b3 = __hadd2(b3, u2h(vb.w));
        }
        for (; k + 2 <= m; k += 2) {
            int ea = __shfl_sync(FULL, idx, k + half);
            uint4 va = g_edge_h[ea * 16 + sub];
            a0 = __hadd2(a0, u2h(va.x)); a1 = __hadd2(a1, u2h(va.y));
            a2 = __hadd2(a2, u2h(va.z)); a3 = __hadd2(a3, u2h(va.w));
        }
        if (k < m) {
            int ea = __shfl_sync(FULL, idx, k);
            if (half == 0) {
                uint4 va = g_edge_h[ea * 16 + sub];
                a0 = __hadd2(a0, u2h(va.x)); a1 = __hadd2(a1, u2h(va.y));
                a2 = __hadd2(a2, u2h(va.z)); a3 = __hadd2(a3, u2h(va.w));
            }
        }
    }
    PDL_TRIGGER();
    a0 = __hadd2(a0, b0); a1 = __hadd2(a1, b1);
    a2 = __hadd2(a2, b2); a3 = __hadd2(a3, b3);
    float2 f0 = __half22float2(a0), f1 = __half22float2(a1);
    float2 f2 = __half22float2(a2), f3 = __half22float2(a3);
    float fs[8] = {f0.x, f0.y, f1.x, f1.y, f2.x, f2.y, f3.x, f3.y};
    #pragma unroll
    for (int i = 0; i < 8; i++) fs[i] += __shfl_xor_sync(FULL, fs[i], 16);

    float s = g_dv_inv[n];
    float4 ra = __ldg(&x0[n * 32 + 2 * sub]);
    float4 rb = __ldg(&x0[n * 32 + 2 * sub + 1]);
    float y[8];
    y[0] = fs[0] * s + ra.x; y[1] = fs[1] * s + ra.y;
    y[2] = fs[2] * s + ra.z; y[3] = fs[3] * s + ra.w;
    y[4] = fs[4] * s + rb.x; y[5] = fs[5] * s + rb.y;
    y[6] = fs[6] * s + rb.z; y[7] = fs[7] * s + rb.w;

    float sm = ((y[0] + y[1]) + (y[2] + y[3])) + ((y[4] + y[5]) + (y[6] + y[7]));
    #pragma unroll
    for (int o = 8; o > 0; o >>= 1) sm += __shfl_xor_sync(FULL, sm, o);
    float mu = sm * (1.0f / D);
    float s2 = 0.f;
    #pragma unroll
    for (int i = 0; i < 8; i++) { float d = y[i] - mu; s2 += d * d; }
    #pragma unroll
    for (int o = 8; o > 0; o >>= 1) s2 += __shfl_xor_sync(FULL, s2, o);
    float rstd = rsqrtf(s2 * (1.0f / D) + LN_EPS);

    float4 ga = __ldg(&gamma4[2 * sub]);
    float4 gb = __ldg(&gamma4[2 * sub + 1]);
    float4 ba = __ldg(&beta4[2 * sub]);
    float4 bb = __ldg(&beta4[2 * sub + 1]);
    float o0 = (y[0] - mu) * rstd * ga.x + ba.x;
    float o1 = (y[1] - mu) * rstd * ga.y + ba.y;
    float o2 = (y[2] - mu) * rstd * ga.z + ba.z;
    float o3 = (y[3] - mu) * rstd * ga.w + ba.w;
    float o4 = (y[4] - mu) * rstd * gb.x + bb.x;
    float o5 = (y[5] - mu) * rstd * gb.y + bb.y;
    float o6 = (y[6] - mu) * rstd * gb.z + bb.z;
    float o7 = (y[7] - mu) * rstd * gb.w + bb.w;
    if (half == 0) {
        __half2 h0 = __floats2half2_rn(o0, o1);
        __half2 h1 = __floats2half2_rn(o2, o3);
        __half2 h2 = __floats2half2_rn(o4, o5);
        __half2 h3 = __floats2half2_rn(o6, o7);
        uint4 pk;
        pk.x = *(unsigned*)&h0; pk.y = *(unsigned*)&h1;
        pk.z = *(unsigned*)&h2; pk.w = *(unsigned*)&h3;
        g_x[n * 16 + sub] = pk;
    }
}

// ---------------- softmax + pool merged: 128 blocks (one per dim), redundant softmax ----------------
__global__ void __launch_bounds__(256) softpool_kernel(float* __restrict__ out) {
    GRID_DEP_SYNC();
    __shared__ float sc[N_EDGES];   // unnormalized scores (20 KB)
    __shared__ float red[8];
    int t = threadIdx.x;
    int d = blockIdx.x;

    // block-wide max over logits
    float m = -1e30f;
    for (int e = t; e < N_EDGES; e += 256) m = fmaxf(m, g_logits[e]);
    #pragma unroll
    for (int o = 16; o > 0; o >>= 1) m = fmaxf(m, __shfl_xor_sync(FULL, m, o));
    if ((t & 31) == 0) red[t >> 5] = m;
    __syncthreads();
    float mx = fmaxf(fmaxf(fmaxf(red[0], red[1]), fmaxf(red[2], red[3])),
                     fmaxf(fmaxf(red[4], red[5]), fmaxf(red[6], red[7])));
    __syncthreads();
    // exp + sum
    float s = 0.0f;
    for (int e = t; e < N_EDGES; e += 256) {
        float v = expf(g_logits[e] - mx);
        sc[e] = v;
        s += v;
    }
    #pragma unroll
    for (int o = 16; o > 0; o >>= 1) s += __shfl_xor_sync(FULL, s, o);
    if ((t & 31) == 0) red[t >> 5] = s;
    __syncthreads();
    float inv = 1.0f / (((red[0] + red[1]) + (red[2] + red[3])) +
                        ((red[4] + red[5]) + (red[6] + red[7])));
    // pool this block's dim
    const float* eo = (const float*)g_edge_out;
    float acc = 0.0f;
    for (int e = t; e < N_EDGES; e += 256)
        acc += sc[e] * eo[e * D + d];
    #pragma unroll
    for (int o = 16; o > 0; o >>= 1) acc += __shfl_xor_sync(FULL, acc, o);
    __syncthreads();
    if ((t & 31) == 0) red[t >> 5] = acc;
    __syncthreads();
    if (t == 0) {
        float ss = ((red[0] + red[1]) + (red[2] + red[3])) +
                   ((red[4] + red[5]) + (red[6] + red[7]));
        out[d] = ss * inv;
    }
}

// ---------------- PDL launch helper ----------------
static cudaLaunchAttribute g_pdl_attr[1];
static inline cudaLaunchConfig_t pdl_cfg(unsigned gx, unsigned bx) {
    cudaLaunchConfig_t cfg = {};
    cfg.gridDim = dim3(gx, 1, 1);
    cfg.blockDim = dim3(bx, 1, 1);
    cfg.dynamicSmemBytes = 0;
    cfg.stream = 0;
    g_pdl_attr[0].id = cudaLaunchAttributeProgrammaticStreamSerialization;
    g_pdl_attr[0].val.programmaticStreamSerializationAllowed = 1;
    cfg.attrs = g_pdl_attr;
    cfg.numAttrs = 1;
    return cfg;
}

// ---------------- launch ----------------
extern "C" void kernel_launch(void* const* d_in, const int* in_sizes, int n_in,
                              void* d_out, int out_size) {
    const float* x0    = (const float*)d_in[0];
    const float* H     = (const float*)d_in[1];
    const float* gamma = (const float*)d_in[2];
    const float* beta  = (const float*)d_in[3];
    const float* W     = (const float*)d_in[4];
    const float* b     = (const float*)d_in[5];
    const float* q     = (const float*)d_in[6];
    float* out = (float*)d_out;

    scan_kernel<<<2500, 256>>>(H, (const float4*)x0);   // first kernel: normal launch

    { cudaLaunchConfig_t c = pdl_cfg(12500, 256);
      cudaLaunchKernelEx(&c, transpose_kernel); }
    { cudaLaunchConfig_t c = pdl_cfg(N_EDGES, 128);
      cudaLaunchKernelEx(&c, emit_kernel); }

    for (int l = 0; l < 4; l++) {
        { cudaLaunchConfig_t c = pdl_cfg(N_EDGES, 128);
          cudaLaunchKernelEx(&c, v2e_kernel<false>, W, b, q); }
        { cudaLaunchConfig_t c = pdl_cfg(N_NODES / 8, 256);
          cudaLaunchKernelEx(&c, e2v_ln_kernel,
                             (const float4*)x0, (const float4*)gamma,
                             (const float4*)beta); }
    }
    { cudaLaunchConfig_t c = pdl_cfg(N_EDGES, 128);
      cudaLaunchKernelEx(&c, v2e_kernel<true>, W, b, q); }   // + fused logits

    { cudaLaunchConfig_t c = pdl_cfg(D, 256);
      cudaLaunchKernelEx(&c, softpool_kernel, out); }
}

// round 16
// speedup vs baseline: 1.0519x; 1.0519x over previous
#include <cuda_runtime.h>
#include <cuda_fp16.h>
#include <math.h>

#define N_NODES 20000
#define N_EDGES 5000
#define D       128
#define ATT     32
#define ECAP    384
#define NCAP    128
#define LN_EPS  1e-5f
#define DEG_EPS 1e-12f
#define FULL    0xffffffffu
#define E4      (N_EDGES / 4)    // 1250 float4 per H row
#define WPR     160              // bitmask words per node row (5120 bits)
#define TWPR    625              // transposed words per edge row (20000 bits)

// ---------------- device scratch ----------------
__device__ int   g_edge_cnt[N_EDGES];
__device__ int   g_node_cnt[N_NODES];
__device__ int   g_edge_nodes[N_EDGES * ECAP];
__device__ int   g_node_edges[N_NODES * NCAP];
__device__ unsigned g_bits [N_NODES * WPR];    // 12.8 MB node-major bitmask
__device__ unsigned g_bitsT[5120 * TWPR];      // 12.8 MB edge-major bitmask
__device__ float g_de_inv[N_EDGES];
__device__ float g_dv_inv[N_NODES];
__device__ uint4  g_x[N_NODES * 16];           // fp16 features (256B rows, 16 uint4)
__device__ uint4  g_edge_h[N_EDGES * 16];      // fp16 edge means
__device__ float4 g_edge_out[N_EDGES * 32];    // fp32 final edge_out
__device__ float g_logits[N_EDGES];
__device__ float g_scores[N_EDGES];

// ---------------- fp16 helpers ----------------
__device__ __forceinline__ uint2 f4_to_h4(float4 v) {
    __half2 a = __floats2half2_rn(v.x, v.y);
    __half2 b = __floats2half2_rn(v.z, v.w);
    uint2 r; r.x = *(unsigned*)&a; r.y = *(unsigned*)&b; return r;
}
__device__ __forceinline__ __half2 u2h(unsigned u) { return *(__half2*)&u; }
__device__ __forceinline__ void add8(float* fs, uint4 v) {
    float2 f0 = __half22float2(u2h(v.x));
    float2 f1 = __half22float2(u2h(v.y));
    float2 f2 = __half22float2(u2h(v.z));
    float2 f3 = __half22float2(u2h(v.w));
    fs[0] += f0.x; fs[1] += f0.y; fs[2] += f1.x; fs[3] += f1.y;
    fs[4] += f2.x; fs[5] += f2.y; fs[6] += f3.x; fs[7] += f3.y;
}

// ---------------- phase 1: scan (x0 conversion folded in) ----------------
__global__ void __launch_bounds__(256) scan_kernel(const float* __restrict__ H,
                                                   const float4* __restrict__ x0) {
    // folded init: x0 -> fp16
    {
        int i = blockIdx.x * blockDim.x + threadIdx.x;
        int stride = gridDim.x * blockDim.x;
        uint2* xp = (uint2*)g_x;
        for (int k = i; k < N_NODES * 32; k += stride) xp[k] = f4_to_h4(__ldg(&x0[k]));
    }
    int gw = (blockIdx.x * blockDim.x + threadIdx.x) >> 5;
    int lane = threadIdx.x & 31;
    if (gw >= N_NODES) return;
    const float4* row = (const float4*)H + (size_t)gw * E4;
    int* nlist = &g_node_edges[gw * NCAP];
    unsigned* brow = &g_bits[gw * WPR];
    unsigned lt = (1u << lane) - 1u;
    int nbase = 0;
    for (int c = 0; c < 10; c++) {
        float4 v[4];
        #pragma unroll
        for (int u = 0; u < 4; u++) {
            int i = (c * 4 + u) * 32 + lane;
            v[u] = make_float4(0.f, 0.f, 0.f, 0.f);
            if (i < E4) v[u] = __ldg(&row[i]);
        }
        #pragma unroll
        for (int u = 0; u < 4; u++) {
            int g = c * 4 + u;
            int i = g * 32 + lane;
            unsigned b0 = __ballot_sync(FULL, v[u].x != 0.f);
            unsigned b1 = __ballot_sync(FULL, v[u].y != 0.f);
            unsigned b2 = __ballot_sync(FULL, v[u].z != 0.f);
            unsigned b3 = __ballot_sync(FULL, v[u].w != 0.f);
            unsigned bw = (lane == 0) ? b0 : (lane == 1) ? b1 : (lane == 2) ? b2 : b3;
            if (lane < 4) brow[4 * g + lane] = bw;
            int p0 = __popc(b0), p1 = __popc(b1), p2 = __popc(b2);
            int total = p0 + p1 + p2 + __popc(b3);
            int e = i * 4;
            int slot;
            if (v[u].x != 0.f) { slot = nbase + __popc(b0 & lt);
                                 if (slot < NCAP) nlist[slot] = e; }
            if (v[u].y != 0.f) { slot = nbase + p0 + __popc(b1 & lt);
                                 if (slot < NCAP) nlist[slot] = e + 1; }
            if (v[u].z != 0.f) { slot = nbase + p0 + p1 + __popc(b2 & lt);
                                 if (slot < NCAP) nlist[slot] = e + 2; }
            if (v[u].w != 0.f) { slot = nbase + p0 + p1 + p2 + __popc(b3 & lt);
                                 if (slot < NCAP) nlist[slot] = e + 3; }
            nbase += total;
        }
    }
    if (lane == 0) {
        g_node_cnt[gw] = nbase;
        g_dv_inv[gw] = 1.0f / fmaxf((float)nbase, DEG_EPS);
    }
}

// ---------------- phase 2: 32x32 bit-tile transpose ----------------
__global__ void __launch_bounds__(256) transpose_kernel() {
    int warp = (blockIdx.x * blockDim.x + threadIdx.x) >> 5;
    if (warp >= TWPR * WPR) return;
    int I = warp / WPR;
    int J = warp - I * WPR;
    int lane = threadIdx.x & 31;
    unsigned x = g_bits[(I * 32 + lane) * WPR + J];
    #pragma unroll
    for (int s = 16; s > 0; s >>= 1) {
        unsigned m = (s == 16) ? 0x0000FFFFu : (s == 8) ? 0x00FF00FFu :
                     (s == 4) ? 0x0F0F0F0Fu : (s == 2) ? 0x33333333u : 0x55555555u;
        unsigned y = __shfl_xor_sync(FULL, x, s);
        x = ((lane & s) == 0) ? ((x & m) | ((y & m) << s))
                              : ((x & ~m) | ((y & ~m) >> s));
    }
    g_bitsT[(J * 32 + lane) * TWPR + I] = x;
}

// ---------------- phase 3: 4 warps/edge emit ----------------
#define QW 157
__global__ void __launch_bounds__(128) emit_kernel() {
    int e = blockIdx.x;
    int w = threadIdx.x >> 5;
    int lane = threadIdx.x & 31;
    int g = e >> 7, rem = e & 127;
    int r = 128 * g + 32 * (rem & 3) + (rem >> 2);
    const unsigned* row = &g_bitsT[r * TWPR];
    int* lst = &g_edge_nodes[e * ECAP];
    __shared__ int wtot[4];

    int q0 = w * QW;
    int q1 = min(q0 + QW, TWPR);

    int cnt = 0;
    for (int i = q0 + lane; i < q1; i += 32) cnt += __popc(row[i]);
    #pragma unroll
    for (int o = 16; o > 0; o >>= 1) cnt += __shfl_xor_sync(FULL, cnt, o);
    if (lane == 0) wtot[w] = cnt;
    __syncthreads();
    int base = 0;
    #pragma unroll
    for (int j = 0; j < 4; j++) if (j < w) base += wtot[j];

    int nbase = base;
    for (int b = q0; b < q1; b += 32) {
        int i = b + lane;
        unsigned word = (i < q1) ? row[i] : 0u;
        int c = __popc(word);
        int pref = c;
        #pragma unroll
        for (int o = 1; o < 32; o <<= 1) {
            int t = __shfl_up_sync(FULL, pref, o);
            if (lane >= o) pref += t;
        }
        int total = __shfl_sync(FULL, pref, 31);
        int slot = nbase + pref - c;
        while (word) {
            int bb = __ffs(word) - 1;
            word &= word - 1;
            if (slot < ECAP) lst[slot] = i * 32 + bb;
            slot++;
        }
        nbase += total;
    }
    if (w == 3 && lane == 0) {
        int tot = wtot[0] + wtot[1] + wtot[2] + wtot[3];
        g_edge_cnt[e] = tot;
        g_de_inv[e] = 1.0f / fmaxf((float)tot, DEG_EPS);
    }
}

// ---------------- V -> E mean: 4 warps/edge, MLP=4 paired LDG.128; FINAL + logits ----------------
template <bool FINAL>
__global__ void __launch_bounds__(128) v2e_kernel(const float* __restrict__ W,
                                                  const float* __restrict__ bA,
                                                  const float* __restrict__ qA) {
    int e = blockIdx.x;
    int w = threadIdx.x >> 5;
    int lane = threadIdx.x & 31;
    int half = lane >> 4;
    int sub = lane & 15;
    __shared__ float part[4][128];

    int deg = min(g_edge_cnt[e], ECAP);
    const int* lst = &g_edge_nodes[e * ECAP];
    int q = (deg + 3) >> 2;
    int start = w * q;
    int end = min(start + q, deg);

    __half2 z = __floats2half2_rn(0.f, 0.f);
    __half2 a0 = z, a1 = z, a2 = z, a3 = z, b0 = z, b1 = z, b2 = z, b3 = z;
    float fs[8] = {0.f, 0.f, 0.f, 0.f, 0.f, 0.f, 0.f, 0.f};

    for (int base = start; base < end; base += 32) {
        int m = min(32, end - base);
        int idx = lst[base + min(lane, m - 1)];
        int k = 0;
        // MLP=4: four independent LDG.128 in flight, accumulators stay at 8 half2
        for (; k + 8 <= m; k += 8) {
            int na = __shfl_sync(FULL, idx, k + half);
            int nb = __shfl_sync(FULL, idx, k + 2 + half);
            int nc = __shfl_sync(FULL, idx, k + 4 + half);
            int nd = __shfl_sync(FULL, idx, k + 6 + half);
            uint4 va = g_x[na * 16 + sub];
            uint4 vb = g_x[nb * 16 + sub];
            uint4 vc = g_x[nc * 16 + sub];
            uint4 vd = g_x[nd * 16 + sub];
            if (FINAL) {
                add8(fs, va); add8(fs, vb); add8(fs, vc); add8(fs, vd);
            } else {
                a0 = __hadd2(a0, u2h(va.x)); a1 = __hadd2(a1, u2h(va.y));
                a2 = __hadd2(a2, u2h(va.z)); a3 = __hadd2(a3, u2h(va.w));
                b0 = __hadd2(b0, u2h(vb.x)); b1 = __hadd2(b1, u2h(vb.y));
                b2 = __hadd2(b2, u2h(vb.z)); b3 = __hadd2(b3, u2h(vb.w));
                a0 = __hadd2(a0, u2h(vc.x)); a1 = __hadd2(a1, u2h(vc.y));
                a2 = __hadd2(a2, u2h(vc.z)); a3 = __hadd2(a3, u2h(vc.w));
                b0 = __hadd2(b0, u2h(vd.x)); b1 = __hadd2(b1, u2h(vd.y));
                b2 = __hadd2(b2, u2h(vd.z)); b3 = __hadd2(b3, u2h(vd.w));
            }
        }
        for (; k + 4 <= m; k += 4) {
            int na = __shfl_sync(FULL, idx, k + half);
            int nb = __shfl_sync(FULL, idx, k + 2 + half);
            uint4 va = g_x[na * 16 + sub];
            uint4 vb = g_x[nb * 16 + sub];
            if (FINAL) {
                add8(fs, va); add8(fs, vb);
            } else {
                a0 = __hadd2(a0, u2h(va.x)); a1 = __hadd2(a1, u2h(va.y));
                a2 = __hadd2(a2, u2h(va.z)); a3 = __hadd2(a3, u2h(va.w));
                b0 = __hadd2(b0, u2h(vb.x)); b1 = __hadd2(b1, u2h(vb.y));
                b2 = __hadd2(b2, u2h(vb.z)); b3 = __hadd2(b3, u2h(vb.w));
            }
        }
        for (; k + 2 <= m; k += 2) {
            int na = __shfl_sync(FULL, idx, k + half);
            uint4 va = g_x[na * 16 + sub];
            if (FINAL) {
                add8(fs, va);
            } else {
                a0 = __hadd2(a0, u2h(va.x)); a1 = __hadd2(a1, u2h(va.y));
                a2 = __hadd2(a2, u2h(va.z)); a3 = __hadd2(a3, u2h(va.w));
            }
        }
        if (k < m) {
            int na = __shfl_sync(FULL, idx, k);
            if (half == 0) {
                uint4 va = g_x[na * 16 + sub];
                if (FINAL) {
                    add8(fs, va);
                } else {
                    a0 = __hadd2(a0, u2h(va.x)); a1 = __hadd2(a1, u2h(va.y));
                    a2 = __hadd2(a2, u2h(va.z)); a3 = __hadd2(a3, u2h(va.w));
                }
            }
        }
    }
    if (!FINAL) {
        a0 = __hadd2(a0, b0); a1 = __hadd2(a1, b1);
        a2 = __hadd2(a2, b2); a3 = __hadd2(a3, b3);
        float2 f0 = __half22float2(a0), f1 = __half22float2(a1);
        float2 f2 = __half22float2(a2), f3 = __half22float2(a3);
        fs[0] = f0.x; fs[1] = f0.y; fs[2] = f1.x; fs[3] = f1.y;
        fs[4] = f2.x; fs[5] = f2.y; fs[6] = f3.x; fs[7] = f3.y;
    }
    // cross-half merge
    #pragma unroll
    for (int i = 0; i < 8; i++) fs[i] += __shfl_xor_sync(FULL, fs[i], 16);
    if (half == 0) {
        #pragma unroll
        for (int i = 0; i < 8; i++) part[w][sub * 8 + i] = fs[i];
    }
    __syncthreads();
    if (w == 0) {
        float4 p0 = *(const float4*)&part[0][lane * 4];
        float4 p1 = *(const float4*)&part[1][lane * 4];
        float4 p2 = *(const float4*)&part[2][lane * 4];
        float4 p3 = *(const float4*)&part[3][lane * 4];
        float s = g_de_inv[e];
        float4 r;
        r.x = ((p0.x + p1.x) + (p2.x + p3.x)) * s;
        r.y = ((p0.y + p1.y) + (p2.y + p3.y)) * s;
        r.z = ((p0.z + p1.z) + (p2.z + p3.z)) * s;
        r.w = ((p0.w + p1.w) + (p2.w + p3.w)) * s;
        if (FINAL) {
            g_edge_out[e * 32 + lane] = r;
            // fused logits: warp 0 holds the full 128-dim row (4 dims/lane)
            float acc = 0.0f;
            #pragma unroll 8
            for (int k = 0; k < 32; k++) {
                float fx = __shfl_sync(FULL, r.x, k);
                float fy = __shfl_sync(FULL, r.y, k);
                float fz = __shfl_sync(FULL, r.z, k);
                float fw = __shfl_sync(FULL, r.w, k);
                acc += fx * __ldg(&W[(4 * k + 0) * ATT + lane]);
                acc += fy * __ldg(&W[(4 * k + 1) * ATT + lane]);
                acc += fz * __ldg(&W[(4 * k + 2) * ATT + lane]);
                acc += fw * __ldg(&W[(4 * k + 3) * ATT + lane]);
            }
            float t = tanhf(acc + __ldg(&bA[lane])) * __ldg(&qA[lane]);
            #pragma unroll
            for (int o = 16; o > 0; o >>= 1) t += __shfl_xor_sync(FULL, t, o);
            if (lane == 0) g_logits[e] = t;
        } else {
            ((uint2*)g_edge_h)[e * 32 + lane] = f4_to_h4(r);
        }
    }
}

// ---------------- E -> V mean + residual + LayerNorm: warp/node, MLP=4 ----------------
__global__ void __launch_bounds__(256) e2v_ln_kernel(const float4* __restrict__ x0,
                                                     const float4* __restrict__ gamma4,
                                                     const float4* __restrict__ beta4) {
    int n = (blockIdx.x * blockDim.x + threadIdx.x) >> 5;
    int lane = threadIdx.x & 31;
    int half = lane >> 4;
    int sub = lane & 15;
    int deg = min(g_node_cnt[n], NCAP);
    const int* lst = &g_node_edges[n * NCAP];

    __half2 z = __floats2half2_rn(0.f, 0.f);
    __half2 a0 = z, a1 = z, a2 = z, a3 = z, b0 = z, b1 = z, b2 = z, b3 = z;

    for (int base = 0; base < deg; base += 32) {
        int m = min(32, deg - base);
        int idx = lst[base + min(lane, m - 1)];
        int k = 0;
        for (; k + 8 <= m; k += 8) {
            int ea = __shfl_sync(FULL, idx, k + half);
            int eb = __shfl_sync(FULL, idx, k + 2 + half);
            int ec = __shfl_sync(FULL, idx, k + 4 + half);
            int ed = __shfl_sync(FULL, idx, k + 6 + half);
            uint4 va = g_edge_h[ea * 16 + sub];
            uint4 vb = g_edge_h[eb * 16 + sub];
            uint4 vc = g_edge_h[ec * 16 + sub];
            uint4 vd = g_edge_h[ed * 16 + sub];
            a0 = __hadd2(a0, u2h(va.x)); a1 = __hadd2(a1, u2h(va.y));
            a2 = __hadd2(a2, u2h(va.z)); a3 = __hadd2(a3, u2h(va.w));
            b0 = __hadd2(b0, u2h(vb.x)); b1 = __hadd2(b1, u2h(vb.y));
            b2 = __hadd2(b2, u2h(vb.z)); b3 = __hadd2(b3, u2h(vb.w));
            a0 = __hadd2(a0, u2h(vc.x)); a1 = __hadd2(a1, u2h(vc.y));
            a2 = __hadd2(a2, u2h(vc.z)); a3 = __hadd2(a3, u2h(vc.w));
            b0 = __hadd2(b0, u2h(vd.x)); b1 = __hadd2(b1, u2h(vd.y));
            b2 = __hadd2(b2, u2h(vd.z)); b3 = __hadd2(b3, u2h(vd.w));
        }
        for (; k + 4 <= m; k += 4) {
            int ea = __shfl_sync(FULL, idx, k + half);
            int eb = __shfl_sync(FULL, idx, k + 2 + half);
            uint4 va = g_edge_h[ea * 16 + sub];
            uint4 vb = g_edge_h[eb * 16 + sub];
            a0 = __hadd2(a0, u2h(va.x)); a1 = __hadd2(a1, u2h(va.y));
            a2 = __hadd2(a2, u2h(va.z)); a3 = __hadd2(a3, u2h(va.w));
            b0 = __hadd2(b0, u2h(vb.x)); b1 = __hadd2(b1, u2h(vb.y));
            b2 = __hadd2(b2, u2h(vb.z)); b3 = __hadd2(b3, u2h(vb.w));
        }
        for (; k + 2 <= m; k += 2) {
            int ea = __shfl_sync(FULL, idx, k + half);
            uint4 va = g_edge_h[ea * 16 + sub];
            a0 = __hadd2(a0, u2h(va.x)); a1 = __hadd2(a1, u2h(va.y));
            a2 = __hadd2(a2, u2h(va.z)); a3 = __hadd2(a3, u2h(va.w));
        }
        if (k < m) {
            int ea = __shfl_sync(FULL, idx, k);
            if (half == 0) {
                uint4 va = g_edge_h[ea * 16 + sub];
                a0 = __hadd2(a0, u2h(va.x)); a1 = __hadd2(a1, u2h(va.y));
                a2 = __hadd2(a2, u2h(va.z)); a3 = __hadd2(a3, u2h(va.w));
            }
        }
    }
    a0 = __hadd2(a0, b0); a1 = __hadd2(a1, b1);
    a2 = __hadd2(a2, b2); a3 = __hadd2(a3, b3);
    float2 f0 = __half22float2(a0), f1 = __half22float2(a1);
    float2 f2 = __half22float2(a2), f3 = __half22float2(a3);
    float fs[8] = {f0.x, f0.y, f1.x, f1.y, f2.x, f2.y, f3.x, f3.y};
    #pragma unroll
    for (int i = 0; i < 8; i++) fs[i] += __shfl_xor_sync(FULL, fs[i], 16);

    float s = g_dv_inv[n];
    float4 ra = __ldg(&x0[n * 32 + 2 * sub]);
    float4 rb = __ldg(&x0[n * 32 + 2 * sub + 1]);
    float y[8];
    y[0] = fs[0] * s + ra.x; y[1] = fs[1] * s + ra.y;
    y[2] = fs[2] * s + ra.z; y[3] = fs[3] * s + ra.w;
    y[4] = fs[4] * s + rb.x; y[5] = fs[5] * s + rb.y;
    y[6] = fs[6] * s + rb.z; y[7] = fs[7] * s + rb.w;

    float sm = ((y[0] + y[1]) + (y[2] + y[3])) + ((y[4] + y[5]) + (y[6] + y[7]));
    #pragma unroll
    for (int o = 8; o > 0; o >>= 1) sm += __shfl_xor_sync(FULL, sm, o);
    float mu = sm * (1.0f / D);
    float s2 = 0.f;
    #pragma unroll
    for (int i = 0; i < 8; i++) { float d = y[i] - mu; s2 += d * d; }
    #pragma unroll
    for (int o = 8; o > 0; o >>= 1) s2 += __shfl_xor_sync(FULL, s2, o);
    float rstd = rsqrtf(s2 * (1.0f / D) + LN_EPS);

    float4 ga = __ldg(&gamma4[2 * sub]);
    float4 gb = __ldg(&gamma4[2 * sub + 1]);
    float4 ba = __ldg(&beta4[2 * sub]);
    float4 bb = __ldg(&beta4[2 * sub + 1]);
    float o0 = (y[0] - mu) * rstd * ga.x + ba.x;
    float o1 = (y[1] - mu) * rstd * ga.y + ba.y;
    float o2 = (y[2] - mu) * rstd * ga.z + ba.z;
    float o3 = (y[3] - mu) * rstd * ga.w + ba.w;
    float o4 = (y[4] - mu) * rstd * gb.x + bb.x;
    float o5 = (y[5] - mu) * rstd * gb.y + bb.y;
    float o6 = (y[6] - mu) * rstd * gb.z + bb.z;
    float o7 = (y[7] - mu) * rstd * gb.w + bb.w;
    if (half == 0) {
        __half2 h0 = __floats2half2_rn(o0, o1);
        __half2 h1 = __floats2half2_rn(o2, o3);
        __half2 h2 = __floats2half2_rn(o4, o5);
        __half2 h3 = __floats2half2_rn(o6, o7);
        uint4 pk;
        pk.x = *(unsigned*)&h0; pk.y = *(unsigned*)&h1;
        pk.z = *(unsigned*)&h2; pk.w = *(unsigned*)&h3;
        g_x[n * 16 + sub] = pk;
    }
}

// ---------------- softmax over E (single block, R14-exact) ----------------
__global__ void softmax_kernel() {
    __shared__ float red[32];
    int t = threadIdx.x;
    float m = -1e30f;
    for (int e = t; e < N_EDGES; e += blockDim.x) m = fmaxf(m, g_logits[e]);
    #pragma unroll
    for (int o = 16; o > 0; o >>= 1) m = fmaxf(m, __shfl_xor_sync(FULL, m, o));
    if ((t & 31) == 0) red[t >> 5] = m;
    __syncthreads();
    if (t < 32) {
        float v = red[t];
        #pragma unroll
        for (int o = 16; o > 0; o >>= 1) v = fmaxf(v, __shfl_xor_sync(FULL, v, o));
        if (t == 0) red[0] = v;
    }
    __syncthreads();
    float mx = red[0];
    __syncthreads();
    float s = 0.0f;
    for (int e = t; e < N_EDGES; e += blockDim.x) s += expf(g_logits[e] - mx);
    #pragma unroll
    for (int o = 16; o > 0; o >>= 1) s += __shfl_xor_sync(FULL, s, o);
    if ((t & 31) == 0) red[t >> 5] = s;
    __syncthreads();
    if (t < 32) {
        float v = red[t];
        #pragma unroll
        for (int o = 16; o > 0; o >>= 1) v += __shfl_xor_sync(FULL, v, o);
        if (t == 0) red[0] = v;
    }
    __syncthreads();
    float inv = 1.0f / red[0];
    for (int e = t; e < N_EDGES; e += blockDim.x)
        g_scores[e] = expf(g_logits[e] - mx) * inv;
}

// ---------------- pooled output: 128 blocks (one per dim), R14-exact ----------------
__global__ void pool_kernel(float* __restrict__ out) {
    int d = blockIdx.x;
    int t = threadIdx.x;
    const float* eo = (const float*)g_edge_out;
    float acc = 0.0f;
    for (int e = t; e < N_EDGES; e += blockDim.x)
        acc += g_scores[e] * eo[e * D + d];
    __shared__ float red[8];
    #pragma unroll
    for (int o = 16; o > 0; o >>= 1) acc += __shfl_xor_sync(FULL, acc, o);
    if ((t & 31) == 0) red[t >> 5] = acc;
    __syncthreads();
    if (t == 0) {
        float s = 0.0f;
        for (int w = 0; w < (blockDim.x >> 5); w++) s += red[w];
        out[d] = s;
    }
}

// ---------------- launch ----------------
extern "C" void kernel_launch(void* const* d_in, const int* in_sizes, int n_in,
                              void* d_out, int out_size) {
    const float* x0    = (const float*)d_in[0];
    const float* H     = (const float*)d_in[1];
    const float* gamma = (const float*)d_in[2];
    const float* beta  = (const float*)d_in[3];
    const float* W     = (const float*)d_in[4];
    const float* b     = (const float*)d_in[5];
    const float* q     = (const float*)d_in[6];
    float* out = (float*)d_out;

    scan_kernel<<<2500, 256>>>(H, (const float4*)x0);   // init folded in
    transpose_kernel<<<12500, 256>>>();
    emit_kernel<<<N_EDGES, 128>>>();

    for (int l = 0; l < 4; l++) {
        v2e_kernel<false><<<N_EDGES, 128>>>(W, b, q);
        e2v_ln_kernel<<<N_NODES / 8, 256>>>((const float4*)x0,
                                            (const float4*)gamma,
                                            (const float4*)beta);
    }
    v2e_kernel<true><<<N_EDGES, 128>>>(W, b, q);   // + fused logits

    softmax_kernel<<<1, 1024>>>();
    pool_kernel<<<D, 256>>>(out);
}